// round 2
// baseline (speedup 1.0000x reference)
#include <cuda_runtime.h>

#define NN 32768
#define GG 256
#define PP 128
#define EE 524288
#define HH 64
#define ROWS (GG*(PP-1))   // 32512

// ---- device scratch (no allocs allowed) ----
__device__ __align__(16) float g_h[NN*HH];   // node features (8MB)
__device__ __align__(16) float g_m[NN*HH];   // messages / later y1 scratch (8MB)
__device__ __align__(16) float g_AT[HH*HH];  // (W4_left @ W3) transposed [k][o]
__device__ __align__(16) float g_BT[HH*HH];  // (W4_right @ W2) transposed [k][o]
__device__ float g_c[HH];
__device__ int   g_is64;

// ---- detect whether edge_index is int64 or int32 ----
__global__ void k_detect(const int* ei32) {
    if (threadIdx.x == 0 && blockIdx.x == 0) {
        int all0 = 1;
        for (int i = 0; i < 4096; i += 2) {
            if (ei32[i + 1] != 0) { all0 = 0; break; }
        }
        g_is64 = all0;   // int64 little-endian: high words of small values are 0
    }
}

// ---- precompute fused layer weights ----
__global__ void k_pre(const float* __restrict__ W2, const float* __restrict__ b2,
                      const float* __restrict__ W3, const float* __restrict__ b3,
                      const float* __restrict__ W4, const float* __restrict__ b4) {
    int tid = threadIdx.x;
    for (int u = 0; u < 16; ++u) {
        int e = tid + 256 * u;       // 4096 entries
        int o = e >> 6, k = e & 63;
        float a = 0.f, b = 0.f;
        for (int t = 0; t < 64; ++t) {
            a += W4[o*128 + t]      * W3[t*64 + k];
            b += W4[o*128 + 64 + t] * W2[t*64 + k];
        }
        g_AT[k*64 + o] = a;
        g_BT[k*64 + o] = b;
    }
    if (tid < 64) {
        float c = b4[tid];
        for (int t = 0; t < 64; ++t)
            c += W4[tid*128 + t]*b3[t] + W4[tid*128 + 64 + t]*b2[t];
        g_c[tid] = c;
    }
}

// ---- input layer: h = normalize(relu(x @ W1.T + b1)) ----
__global__ void k_in(const float* __restrict__ x, const float* __restrict__ W1,
                     const float* __restrict__ b1) {
    __shared__ __align__(16) float sW[8*64];   // [j][o]
    __shared__ float sb[64];
    int tid = threadIdx.x;
    for (int e = tid; e < 512; e += 256) {     // FIX: was `if (tid < 512)` with 256 threads
        int o = e >> 3, j = e & 7;
        sW[j*64 + o] = W1[e];
    }
    if (tid < 64) sb[tid] = b1[tid];
    __syncthreads();
    int lane = tid & 31, warp = tid >> 5;
    for (int node = blockIdx.x*8 + warp; node < NN; node += gridDim.x*8) {
        float xv = (lane < 8) ? x[node*8 + lane] : 0.f;
        float a0 = sb[2*lane], a1 = sb[2*lane + 1];
        #pragma unroll
        for (int j = 0; j < 8; ++j) {
            float xj = __shfl_sync(0xffffffffu, xv, j);
            a0 += sW[j*64 + 2*lane]     * xj;
            a1 += sW[j*64 + 2*lane + 1] * xj;
        }
        a0 = fmaxf(a0, 0.f); a1 = fmaxf(a1, 0.f);
        float s = a0*a0 + a1*a1;
        #pragma unroll
        for (int off = 16; off; off >>= 1) s += __shfl_xor_sync(0xffffffffu, s, off);
        float rn = rsqrtf(s);
        ((float2*)g_h)[node*32 + lane] = make_float2(a0*rn, a1*rn);
    }
}

// ---- scatter: m[dst] += h[src], 16 threads/edge, vector red ----
__global__ void k_scat(const void* __restrict__ ei) {
    int t = blockIdx.x*256 + threadIdx.x;  // EE*16 threads
    int e = t >> 4, q = t & 15;
    int src, dst;
    if (g_is64) {
        const long long* p = (const long long*)ei;
        int v = 0;
        if (q < 2) v = (int)p[q == 0 ? e : EE + e];
        src = __shfl_sync(0xffffffffu, v, 0, 16);
        dst = __shfl_sync(0xffffffffu, v, 1, 16);
    } else {
        const int* p = (const int*)ei;
        int v = 0;
        if (q < 2) v = p[q == 0 ? e : EE + e];
        src = __shfl_sync(0xffffffffu, v, 0, 16);
        dst = __shfl_sync(0xffffffffu, v, 1, 16);
    }
    const float4 v4 = *(const float4*)(g_h + src*64 + q*4);
    float* p = g_m + dst*64 + q*4;
    asm volatile("red.global.add.v4.f32 [%0], {%1,%2,%3,%4};"
                 :: "l"(p), "f"(v4.x), "f"(v4.y), "f"(v4.z), "f"(v4.w) : "memory");
}

// ---- update: h = normalize(relu(A@m + B@h + c)) ----
__global__ void k_upd() {
    __shared__ __align__(16) float sA[64*64];
    __shared__ __align__(16) float sB[64*64];
    __shared__ float sc[64];
    int tid = threadIdx.x;
    for (int e = tid; e < 4096; e += 256) { sA[e] = g_AT[e]; sB[e] = g_BT[e]; }
    if (tid < 64) sc[tid] = g_c[tid];
    __syncthreads();
    int lane = tid & 31, warp = tid >> 5;
    for (int node = blockIdx.x*8 + warp; node < NN; node += gridDim.x*8) {
        float m_lo = g_m[node*64 + lane],      m_hi = g_m[node*64 + 32 + lane];
        float h_lo = g_h[node*64 + lane],      h_hi = g_h[node*64 + 32 + lane];
        float a0 = sc[2*lane], a1 = sc[2*lane + 1];
        #pragma unroll
        for (int k = 0; k < 32; ++k) {
            float mk = __shfl_sync(0xffffffffu, m_lo, k);
            float hk = __shfl_sync(0xffffffffu, h_lo, k);
            float2 av = *(float2*)&sA[k*64 + 2*lane];
            float2 bv = *(float2*)&sB[k*64 + 2*lane];
            a0 += av.x*mk + bv.x*hk;
            a1 += av.y*mk + bv.y*hk;
        }
        #pragma unroll
        for (int k = 0; k < 32; ++k) {
            float mk = __shfl_sync(0xffffffffu, m_hi, k);
            float hk = __shfl_sync(0xffffffffu, h_hi, k);
            float2 av = *(float2*)&sA[(k + 32)*64 + 2*lane];
            float2 bv = *(float2*)&sB[(k + 32)*64 + 2*lane];
            a0 += av.x*mk + bv.x*hk;
            a1 += av.y*mk + bv.y*hk;
        }
        a0 = fmaxf(a0, 0.f); a1 = fmaxf(a1, 0.f);
        float s = a0*a0 + a1*a1;
        #pragma unroll
        for (int off = 16; off; off >>= 1) s += __shfl_xor_sync(0xffffffffu, s, off);
        float rn = rsqrtf(s);
        ((float2*)g_h)[node*32 + lane] = make_float2(a0*rn, a1*rn);
    }
}

// ---- bilinear readout: per graph Ag = einsum(W5, last); y1 = others @ Ag.T + b5 ----
__global__ void k_outer(const float* __restrict__ W5, const float* __restrict__ b5) {
    __shared__ __align__(16) float sAgT[64*64];  // [i][o]
    __shared__ float sLast[64];
    __shared__ float sb5[64];
    int g = blockIdx.x, tid = threadIdx.x;
    if (tid < 64) { sLast[tid] = g_h[(g*128 + 127)*64 + tid]; sb5[tid] = b5[tid]; }
    __syncthreads();
    for (int u = 0; u < 16; ++u) {
        int e = tid + 256 * u;               // entry (o,i)
        int o = e >> 6, i = e & 63;
        const float4* wp = (const float4*)(W5 + o*4096 + i*64);
        float acc = 0.f;
        #pragma unroll
        for (int j4 = 0; j4 < 16; ++j4) {
            float4 w = wp[j4];
            acc += w.x*sLast[j4*4] + w.y*sLast[j4*4+1] + w.z*sLast[j4*4+2] + w.w*sLast[j4*4+3];
        }
        sAgT[i*64 + o] = acc;
    }
    __syncthreads();
    int lane = tid & 31, warp = tid >> 5;
    for (int p = warp; p < 127; p += 8) {
        float x_lo = g_h[(g*128 + p)*64 + lane];
        float x_hi = g_h[(g*128 + p)*64 + 32 + lane];
        float a0 = sb5[2*lane], a1 = sb5[2*lane + 1];
        #pragma unroll
        for (int i = 0; i < 32; ++i) {
            float xi = __shfl_sync(0xffffffffu, x_lo, i);
            float2 av = *(float2*)&sAgT[i*64 + 2*lane];
            a0 += av.x*xi; a1 += av.y*xi;
        }
        #pragma unroll
        for (int i = 0; i < 32; ++i) {
            float xi = __shfl_sync(0xffffffffu, x_hi, i);
            float2 av = *(float2*)&sAgT[(i + 32)*64 + 2*lane];
            a0 += av.x*xi; a1 += av.y*xi;
        }
        ((float2*)g_m)[(g*127 + p)*32 + lane] = make_float2(a0, a1);  // y1 scratch
    }
}

// ---- head: out = relu(y1 @ Wd1.T + bd1) @ Wd2.T + bd2 ----
__global__ void k_head(const float* __restrict__ Wd1, const float* __restrict__ bd1,
                       const float* __restrict__ Wd2, const float* __restrict__ bd2,
                       float* __restrict__ out) {
    __shared__ __align__(16) float sW1T[64*128];  // [k][j]
    __shared__ __align__(16) float sb1[128];
    __shared__ __align__(16) float sW2[128];
    int tid = threadIdx.x;
    for (int e = tid; e < 8192; e += 256) {
        int j = e >> 6, k = e & 63;
        sW1T[k*128 + j] = Wd1[e];
    }
    if (tid < 128) { sb1[tid] = bd1[tid]; sW2[tid] = Wd2[tid]; }
    __syncthreads();
    float bias2 = bd2[0];
    int lane = tid & 31, warp = tid >> 5;
    for (int row = blockIdx.x*8 + warp; row < ROWS; row += gridDim.x*8) {
        float y_lo = g_m[row*64 + lane], y_hi = g_m[row*64 + 32 + lane];
        float4 z = *(float4*)&sb1[4*lane];
        #pragma unroll
        for (int k = 0; k < 32; ++k) {
            float yk = __shfl_sync(0xffffffffu, y_lo, k);
            float4 w = *(float4*)&sW1T[k*128 + 4*lane];
            z.x += w.x*yk; z.y += w.y*yk; z.z += w.z*yk; z.w += w.w*yk;
        }
        #pragma unroll
        for (int k = 0; k < 32; ++k) {
            float yk = __shfl_sync(0xffffffffu, y_hi, k);
            float4 w = *(float4*)&sW1T[(k + 32)*128 + 4*lane];
            z.x += w.x*yk; z.y += w.y*yk; z.z += w.z*yk; z.w += w.w*yk;
        }
        float4 w2 = *(float4*)&sW2[4*lane];
        float acc = fmaxf(z.x, 0.f)*w2.x + fmaxf(z.y, 0.f)*w2.y +
                    fmaxf(z.z, 0.f)*w2.z + fmaxf(z.w, 0.f)*w2.w;
        #pragma unroll
        for (int off = 16; off; off >>= 1) acc += __shfl_xor_sync(0xffffffffu, acc, off);
        if (lane == 0) out[row] = acc + bias2;
    }
}

extern "C" void kernel_launch(void* const* d_in, const int* in_sizes, int n_in,
                              void* d_out, int out_size) {
    const float* x = (const float*)d_in[0];
    const void*  ei = d_in[1];
    // d_in[2] = batch (unused: batch = arange(N)/P is deterministic)
    int base = (in_sizes[3] == 1) ? 4 : 3;   // num_graphs scalar present or not
    const float* W1  = (const float*)d_in[base + 0];
    const float* b1  = (const float*)d_in[base + 1];
    const float* W2  = (const float*)d_in[base + 2];
    const float* b2  = (const float*)d_in[base + 3];
    const float* W3  = (const float*)d_in[base + 4];
    const float* b3  = (const float*)d_in[base + 5];
    const float* W4  = (const float*)d_in[base + 6];
    const float* b4  = (const float*)d_in[base + 7];
    const float* W5  = (const float*)d_in[base + 8];
    const float* b5  = (const float*)d_in[base + 9];
    const float* Wd1 = (const float*)d_in[base + 10];
    const float* bd1 = (const float*)d_in[base + 11];
    const float* Wd2 = (const float*)d_in[base + 12];
    const float* bd2 = (const float*)d_in[base + 13];
    float* out = (float*)d_out;

    void* mptr = nullptr;
    cudaGetSymbolAddress(&mptr, g_m);

    k_detect<<<1, 32>>>((const int*)ei);
    k_pre<<<1, 256>>>(W2, b2, W3, b3, W4, b4);
    k_in<<<512, 256>>>(x, W1, b1);
    for (int d = 0; d < 3; ++d) {
        cudaMemsetAsync(mptr, 0, NN*HH*sizeof(float));
        k_scat<<<EE*16/256, 256>>>(ei);
        k_upd<<<512, 256>>>();
    }
    k_outer<<<GG, 256>>>(W5, b5);
    k_head<<<296, 256>>>(Wd1, bd1, Wd2, bd2, out);
}

// round 3
// speedup vs baseline: 1.1576x; 1.1576x over previous
#include <cuda_runtime.h>

#define NN 32768
#define GG 256
#define PP 128
#define EE 524288
#define HH 64
#define ROWS (GG*(PP-1))   // 32512

// ---- device scratch (no allocs allowed) ----
__device__ __align__(16) float g_h[NN*HH];     // ping buffer (8MB), later y1 scratch
__device__ __align__(16) float g_m[NN*HH];     // pong buffer (8MB), holds final h
__device__ __align__(16) float g_Ag[GG*HH*HH]; // per-graph bilinear matrices (4MB)
__device__ __align__(16) float g_AT[HH*HH];    // (W4_left @ W3) transposed [k][o]
__device__ __align__(16) float g_BT[HH*HH];    // (W4_right @ W2) transposed [k][o]
__device__ float g_c[HH];
__device__ int   g_is64;
// CSR
__device__ int g_cur[NN];      // degree counters -> cursors
__device__ int g_off[NN + 1];
__device__ int g_srcl[EE];     // src ids sorted by dst

// ---- detect whether edge_index is int64 or int32 (parallel) ----
__global__ void k_detect(const int* __restrict__ ei32) {
    int tid = threadIdx.x;  // 1024 threads check 2048 candidate high-words
    int bad = (ei32[2*tid + 1] != 0) | (ei32[2*(tid + 1024) + 1] != 0);
    int any = __syncthreads_or(bad);
    if (tid == 0) g_is64 = !any;
}

// ---- precompute fused layer weights (parallel) ----
__global__ void k_pre(const float* __restrict__ W2, const float* __restrict__ b2,
                      const float* __restrict__ W3, const float* __restrict__ b3,
                      const float* __restrict__ W4, const float* __restrict__ b4) {
    int tid = threadIdx.x;
    if (blockIdx.x < 16) {
        int e = blockIdx.x * 256 + tid;  // 4096 entries
        int o = e >> 6, k = e & 63;
        float a = 0.f, b = 0.f;
        for (int t = 0; t < 64; ++t) {
            a += W4[o*128 + t]      * W3[t*64 + k];
            b += W4[o*128 + 64 + t] * W2[t*64 + k];
        }
        g_AT[k*64 + o] = a;
        g_BT[k*64 + o] = b;
    } else if (tid < 64) {
        float c = b4[tid];
        for (int t = 0; t < 64; ++t)
            c += W4[tid*128 + t]*b3[t] + W4[tid*128 + 64 + t]*b2[t];
        g_c[tid] = c;
    }
}

// ---- input layer: h = normalize(relu(x @ W1.T + b1)) ----
__global__ void k_in(const float* __restrict__ x, const float* __restrict__ W1,
                     const float* __restrict__ b1) {
    __shared__ __align__(16) float sW[8*64];   // [j][o]
    __shared__ float sb[64];
    int tid = threadIdx.x;
    for (int e = tid; e < 512; e += 256) {
        int o = e >> 3, j = e & 7;
        sW[j*64 + o] = W1[e];
    }
    if (tid < 64) sb[tid] = b1[tid];
    __syncthreads();
    int lane = tid & 31, warp = tid >> 5;
    for (int node = blockIdx.x*8 + warp; node < NN; node += gridDim.x*8) {
        float xv = (lane < 8) ? x[node*8 + lane] : 0.f;
        float a0 = sb[2*lane], a1 = sb[2*lane + 1];
        #pragma unroll
        for (int j = 0; j < 8; ++j) {
            float xj = __shfl_sync(0xffffffffu, xv, j);
            a0 += sW[j*64 + 2*lane]     * xj;
            a1 += sW[j*64 + 2*lane + 1] * xj;
        }
        a0 = fmaxf(a0, 0.f); a1 = fmaxf(a1, 0.f);
        float s = a0*a0 + a1*a1;
        #pragma unroll
        for (int off = 16; off; off >>= 1) s += __shfl_xor_sync(0xffffffffu, s, off);
        float rn = rsqrtf(s);
        ((float2*)g_h)[node*32 + lane] = make_float2(a0*rn, a1*rn);
    }
}

// ---- CSR build: histogram, scan, fill ----
__global__ void k_hist(const void* __restrict__ ei) {
    int e = blockIdx.x*256 + threadIdx.x;
    int dst = g_is64 ? (int)((const long long*)ei)[EE + e] : ((const int*)ei)[EE + e];
    atomicAdd(&g_cur[dst], 1);
}

__global__ void k_scan() {   // 1 block, 1024 threads, 32 values each
    __shared__ int part[1024];
    int tid = threadIdx.x;
    int base = tid * 32;
    int loc[32]; int s = 0;
    #pragma unroll
    for (int i = 0; i < 32; ++i) { loc[i] = g_cur[base + i]; s += loc[i]; }
    part[tid] = s;
    __syncthreads();
    for (int off = 1; off < 1024; off <<= 1) {
        int v = (tid >= off) ? part[tid - off] : 0;
        __syncthreads();
        part[tid] += v;
        __syncthreads();
    }
    int run = tid ? part[tid - 1] : 0;
    #pragma unroll
    for (int i = 0; i < 32; ++i) {
        g_off[base + i] = run;
        g_cur[base + i] = run;   // cursor for fill
        run += loc[i];
    }
    if (tid == 1023) g_off[NN] = run;
}

__global__ void k_fill(const void* __restrict__ ei) {
    int e = blockIdx.x*256 + threadIdx.x;
    int src, dst;
    if (g_is64) {
        const long long* p = (const long long*)ei;
        src = (int)p[e]; dst = (int)p[EE + e];
    } else {
        const int* p = (const int*)ei;
        src = p[e]; dst = p[EE + e];
    }
    int pos = atomicAdd(&g_cur[dst], 1);
    g_srcl[pos] = src;
}

// ---- fused gather + update: hout = normalize(relu(A@sum_in(hin) + B@hin + c)) ----
__global__ void k_gup(const float* __restrict__ hin, float* __restrict__ hout) {
    __shared__ __align__(16) float sA[64*64];
    __shared__ __align__(16) float sB[64*64];
    __shared__ float sc[64];
    int tid = threadIdx.x;
    for (int e = tid; e < 4096; e += 256) { sA[e] = g_AT[e]; sB[e] = g_BT[e]; }
    if (tid < 64) sc[tid] = g_c[tid];
    __syncthreads();
    int lane = tid & 31, warp = tid >> 5;
    for (int node = blockIdx.x*8 + warp; node < NN; node += gridDim.x*8) {
        int o0 = g_off[node], o1 = g_off[node + 1];
        float m_lo = 0.f, m_hi = 0.f;
        int e = o0;
        for (; e + 2 <= o1; e += 2) {
            int s0 = g_srcl[e], s1 = g_srcl[e + 1];
            const float* p0 = hin + s0*64;
            const float* p1 = hin + s1*64;
            m_lo += p0[lane] + p1[lane];
            m_hi += p0[32 + lane] + p1[32 + lane];
        }
        if (e < o1) {
            const float* p0 = hin + g_srcl[e]*64;
            m_lo += p0[lane]; m_hi += p0[32 + lane];
        }
        float h_lo = hin[node*64 + lane], h_hi = hin[node*64 + 32 + lane];
        float a0 = sc[2*lane], a1 = sc[2*lane + 1];
        #pragma unroll
        for (int k = 0; k < 32; ++k) {
            float mk = __shfl_sync(0xffffffffu, m_lo, k);
            float hk = __shfl_sync(0xffffffffu, h_lo, k);
            float2 av = *(float2*)&sA[k*64 + 2*lane];
            float2 bv = *(float2*)&sB[k*64 + 2*lane];
            a0 += av.x*mk + bv.x*hk;
            a1 += av.y*mk + bv.y*hk;
        }
        #pragma unroll
        for (int k = 0; k < 32; ++k) {
            float mk = __shfl_sync(0xffffffffu, m_hi, k);
            float hk = __shfl_sync(0xffffffffu, h_hi, k);
            float2 av = *(float2*)&sA[(k + 32)*64 + 2*lane];
            float2 bv = *(float2*)&sB[(k + 32)*64 + 2*lane];
            a0 += av.x*mk + bv.x*hk;
            a1 += av.y*mk + bv.y*hk;
        }
        a0 = fmaxf(a0, 0.f); a1 = fmaxf(a1, 0.f);
        float s = a0*a0 + a1*a1;
        #pragma unroll
        for (int off = 16; off; off >>= 1) s += __shfl_xor_sync(0xffffffffu, s, off);
        float rn = rsqrtf(s);
        ((float2*)hout)[node*32 + lane] = make_float2(a0*rn, a1*rn);
    }
}

// ---- Ag[g][o][i] = sum_j W5[o][i*64+j] * last[g][j]; one block per o-row ----
__global__ void k_ag(const float* __restrict__ W5, const float* __restrict__ hfin) {
    __shared__ __align__(16) float sWT[64*64];  // [j][i]
    int o = blockIdx.x, tid = threadIdx.x;
    for (int e = tid; e < 4096; e += 256) {
        int i = e >> 6, j = e & 63;
        sWT[j*64 + i] = W5[o*4096 + e];
    }
    __syncthreads();
    int lane = tid & 31, warp = tid >> 5;
    for (int g = warp; g < GG; g += 8) {
        const float* lp = hfin + (g*128 + 127)*64;
        float l_lo = lp[lane], l_hi = lp[32 + lane];
        float a0 = 0.f, a1 = 0.f;
        #pragma unroll
        for (int j = 0; j < 32; ++j) {
            float lj = __shfl_sync(0xffffffffu, l_lo, j);
            a0 += sWT[j*64 + lane]      * lj;
            a1 += sWT[j*64 + 32 + lane] * lj;
        }
        #pragma unroll
        for (int j = 0; j < 32; ++j) {
            float lj = __shfl_sync(0xffffffffu, l_hi, j);
            a0 += sWT[(j + 32)*64 + lane]      * lj;
            a1 += sWT[(j + 32)*64 + 32 + lane] * lj;
        }
        g_Ag[g*4096 + o*64 + lane]      = a0;
        g_Ag[g*4096 + o*64 + 32 + lane] = a1;
    }
}

// ---- y1 = others @ Ag.T + b5; one block per graph ----
__global__ void k_y1(const float* __restrict__ hfin, const float* __restrict__ b5,
                     float* __restrict__ y1) {
    __shared__ __align__(16) float sAgT[64*66];  // [i][o], padded stride 66
    __shared__ float sb5[64];
    int g = blockIdx.x, tid = threadIdx.x;
    for (int e = tid; e < 4096; e += 256) {
        int o = e >> 6, i = e & 63;
        sAgT[i*66 + o] = g_Ag[g*4096 + e];
    }
    if (tid < 64) sb5[tid] = b5[tid];
    __syncthreads();
    int lane = tid & 31, warp = tid >> 5;
    for (int p = warp; p < 127; p += 8) {
        const float* xp = hfin + (g*128 + p)*64;
        float x_lo = xp[lane], x_hi = xp[32 + lane];
        float a0 = sb5[2*lane], a1 = sb5[2*lane + 1];
        #pragma unroll
        for (int i = 0; i < 32; ++i) {
            float xi = __shfl_sync(0xffffffffu, x_lo, i);
            float2 av = *(float2*)&sAgT[i*66 + 2*lane];
            a0 += av.x*xi; a1 += av.y*xi;
        }
        #pragma unroll
        for (int i = 0; i < 32; ++i) {
            float xi = __shfl_sync(0xffffffffu, x_hi, i);
            float2 av = *(float2*)&sAgT[(i + 32)*66 + 2*lane];
            a0 += av.x*xi; a1 += av.y*xi;
        }
        ((float2*)y1)[(g*127 + p)*32 + lane] = make_float2(a0, a1);
    }
}

// ---- head: out = relu(y1 @ Wd1.T + bd1) @ Wd2.T + bd2 ----
__global__ void k_head(const float* __restrict__ y1,
                       const float* __restrict__ Wd1, const float* __restrict__ bd1,
                       const float* __restrict__ Wd2, const float* __restrict__ bd2,
                       float* __restrict__ out) {
    __shared__ __align__(16) float sW1T[64*128];  // [k][j]
    __shared__ __align__(16) float sb1[128];
    __shared__ __align__(16) float sW2[128];
    int tid = threadIdx.x;
    for (int e = tid; e < 8192; e += 256) {
        int j = e >> 6, k = e & 63;
        sW1T[k*128 + j] = Wd1[e];
    }
    if (tid < 128) { sb1[tid] = bd1[tid]; sW2[tid] = Wd2[tid]; }
    __syncthreads();
    float bias2 = bd2[0];
    int lane = tid & 31, warp = tid >> 5;
    for (int row = blockIdx.x*8 + warp; row < ROWS; row += gridDim.x*8) {
        float y_lo = y1[row*64 + lane], y_hi = y1[row*64 + 32 + lane];
        float4 z = *(float4*)&sb1[4*lane];
        #pragma unroll
        for (int k = 0; k < 32; ++k) {
            float yk = __shfl_sync(0xffffffffu, y_lo, k);
            float4 w = *(float4*)&sW1T[k*128 + 4*lane];
            z.x += w.x*yk; z.y += w.y*yk; z.z += w.z*yk; z.w += w.w*yk;
        }
        #pragma unroll
        for (int k = 0; k < 32; ++k) {
            float yk = __shfl_sync(0xffffffffu, y_hi, k);
            float4 w = *(float4*)&sW1T[(k + 32)*128 + 4*lane];
            z.x += w.x*yk; z.y += w.y*yk; z.z += w.z*yk; z.w += w.w*yk;
        }
        float4 w2 = *(float4*)&sW2[4*lane];
        float acc = fmaxf(z.x, 0.f)*w2.x + fmaxf(z.y, 0.f)*w2.y +
                    fmaxf(z.z, 0.f)*w2.z + fmaxf(z.w, 0.f)*w2.w;
        #pragma unroll
        for (int off = 16; off; off >>= 1) acc += __shfl_xor_sync(0xffffffffu, acc, off);
        if (lane == 0) out[row] = acc + bias2;
    }
}

extern "C" void kernel_launch(void* const* d_in, const int* in_sizes, int n_in,
                              void* d_out, int out_size) {
    const float* x = (const float*)d_in[0];
    const void*  ei = d_in[1];
    int base = (in_sizes[3] == 1) ? 4 : 3;   // num_graphs scalar present or not
    const float* W1  = (const float*)d_in[base + 0];
    const float* b1  = (const float*)d_in[base + 1];
    const float* W2  = (const float*)d_in[base + 2];
    const float* b2  = (const float*)d_in[base + 3];
    const float* W3  = (const float*)d_in[base + 4];
    const float* b3  = (const float*)d_in[base + 5];
    const float* W4  = (const float*)d_in[base + 6];
    const float* b4  = (const float*)d_in[base + 7];
    const float* W5  = (const float*)d_in[base + 8];
    const float* b5  = (const float*)d_in[base + 9];
    const float* Wd1 = (const float*)d_in[base + 10];
    const float* bd1 = (const float*)d_in[base + 11];
    const float* Wd2 = (const float*)d_in[base + 12];
    const float* bd2 = (const float*)d_in[base + 13];
    float* out = (float*)d_out;

    float *hA = nullptr, *hB = nullptr;
    void* curp = nullptr;
    cudaGetSymbolAddress((void**)&hA, g_h);
    cudaGetSymbolAddress((void**)&hB, g_m);
    cudaGetSymbolAddress(&curp, g_cur);

    k_detect<<<1, 1024>>>((const int*)ei);
    cudaMemsetAsync(curp, 0, NN*sizeof(int));
    k_pre<<<17, 256>>>(W2, b2, W3, b3, W4, b4);
    k_in<<<512, 256>>>(x, W1, b1);
    k_hist<<<EE/256, 256>>>(ei);
    k_scan<<<1, 1024>>>();
    k_fill<<<EE/256, 256>>>(ei);
    k_gup<<<512, 256>>>(hA, hB);   // depth 0: g_h -> g_m
    k_gup<<<512, 256>>>(hB, hA);   // depth 1: g_m -> g_h
    k_gup<<<512, 256>>>(hA, hB);   // depth 2: g_h -> g_m (final h in g_m)
    k_ag<<<64, 256>>>(W5, hB);
    k_y1<<<256, 256>>>(hB, b5, hA);   // y1 scratch in g_h
    k_head<<<296, 256>>>(hA, Wd1, bd1, Wd2, bd2, out);
}

// round 4
// speedup vs baseline: 1.4697x; 1.2696x over previous
#include <cuda_runtime.h>

#define NN 32768
#define GG 256
#define PP 128
#define EE 524288
#define HH 64
#define ROWS (GG*(PP-1))   // 32512

// ---- device scratch (no allocs allowed) ----
__device__ __align__(16) float g_h[NN*HH];     // ping buffer (8MB), later y1 scratch
__device__ __align__(16) float g_m[NN*HH];     // pong buffer (8MB), holds final h
__device__ __align__(16) float g_Ag[GG*HH*HH]; // per-graph bilinear matrices (4MB)
__device__ __align__(16) float g_AB[HH*HH*2];  // packed fused weights [k][l]{a0,a1,b0,b1}
__device__ __align__(16) float g_c[HH];        // fused bias (natural pair layout)
__device__ int   g_is64;
// CSR
__device__ __align__(16) int g_cur[NN];
__device__ __align__(16) int g_off[NN + 4];
__device__ int g_srcl[EE];

// ---- f32x2 helpers ----
__device__ __forceinline__ unsigned long long pk2(float x, float y) {
    unsigned long long r; asm("mov.b64 %0,{%1,%2};" : "=l"(r) : "f"(x), "f"(y)); return r;
}
__device__ __forceinline__ unsigned long long ff2(unsigned long long a, unsigned long long b,
                                                  unsigned long long c) {
    unsigned long long d;
    asm("fma.rn.f32x2 %0,%1,%2,%3;" : "=l"(d) : "l"(a), "l"(b), "l"(c)); return d;
}
__device__ __forceinline__ float2 up2(unsigned long long a) {
    float x, y; asm("mov.b64 {%0,%1},%2;" : "=f"(x), "=f"(y) : "l"(a));
    return make_float2(x, y);
}

// ---- detect int64 vs int32 edge_index ----
__global__ void k_detect(const int* __restrict__ ei32) {
    int tid = threadIdx.x;
    int bad = (ei32[2*tid + 1] != 0) | (ei32[2*(tid + 1024) + 1] != 0);
    int any = __syncthreads_or(bad);
    if (tid == 0) g_is64 = !any;
}

// ---- precompute fused layer weights, packed layout ----
__global__ void k_pre(const float* __restrict__ W2, const float* __restrict__ b2,
                      const float* __restrict__ W3, const float* __restrict__ b3,
                      const float* __restrict__ W4, const float* __restrict__ b4) {
    int tid = threadIdx.x;
    if (blockIdx.x < 16) {
        int e = blockIdx.x * 256 + tid;  // 4096 (o,k) entries
        int o = e >> 6, k = e & 63;
        float a = 0.f, b = 0.f;
        for (int t = 0; t < 64; ++t) {
            a += W4[o*128 + t]      * W3[t*64 + k];
            b += W4[o*128 + 64 + t] * W2[t*64 + k];
        }
        g_AB[k*128 + (o >> 1)*4 + (o & 1)]     = a;
        g_AB[k*128 + (o >> 1)*4 + 2 + (o & 1)] = b;
    } else if (tid < 64) {
        float c = b4[tid];
        for (int t = 0; t < 64; ++t)
            c += W4[tid*128 + t]*b3[t] + W4[tid*128 + 64 + t]*b2[t];
        g_c[tid] = c;
    }
}

// ---- input layer ----
__global__ void k_in(const float* __restrict__ x, const float* __restrict__ W1,
                     const float* __restrict__ b1) {
    __shared__ __align__(16) float sW[8*64];   // [j][o]
    __shared__ float sb[64];
    int tid = threadIdx.x;
    for (int e = tid; e < 512; e += 256) {
        int o = e >> 3, j = e & 7;
        sW[j*64 + o] = W1[e];
    }
    if (tid < 64) sb[tid] = b1[tid];
    __syncthreads();
    int lane = tid & 31, warp = tid >> 5;
    for (int node = blockIdx.x*8 + warp; node < NN; node += gridDim.x*8) {
        float xv = (lane < 8) ? x[node*8 + lane] : 0.f;
        float a0 = sb[2*lane], a1 = sb[2*lane + 1];
        #pragma unroll
        for (int j = 0; j < 8; ++j) {
            float xj = __shfl_sync(0xffffffffu, xv, j);
            a0 += sW[j*64 + 2*lane]     * xj;
            a1 += sW[j*64 + 2*lane + 1] * xj;
        }
        a0 = fmaxf(a0, 0.f); a1 = fmaxf(a1, 0.f);
        float s = a0*a0 + a1*a1;
        #pragma unroll
        for (int off = 16; off; off >>= 1) s += __shfl_xor_sync(0xffffffffu, s, off);
        float rn = rsqrtf(s);
        ((float2*)g_h)[node*32 + lane] = make_float2(a0*rn, a1*rn);
    }
}

// ---- CSR build ----
__global__ void k_hist(const void* __restrict__ ei) {
    int e = blockIdx.x*256 + threadIdx.x;
    int dst = g_is64 ? (int)((const long long*)ei)[EE + e] : ((const int*)ei)[EE + e];
    atomicAdd(&g_cur[dst], 1);
}

__global__ void k_scan() {   // 1 block, 1024 threads, coalesced int4, 8 chunks
    __shared__ int wsum[32];
    int tid = threadIdx.x, lane = tid & 31, wid = tid >> 5;
    int running = 0;
    for (int c = 0; c < 8; ++c) {
        int4 v = ((const int4*)g_cur)[c*1024 + tid];
        int s = v.x + v.y + v.z + v.w;
        int ss = s;
        #pragma unroll
        for (int o = 1; o < 32; o <<= 1) {
            int t = __shfl_up_sync(0xffffffffu, ss, o);
            if (lane >= o) ss += t;
        }
        if (lane == 31) wsum[wid] = ss;
        __syncthreads();
        if (wid == 0) {
            int w = wsum[lane];
            #pragma unroll
            for (int o = 1; o < 32; o <<= 1) {
                int t = __shfl_up_sync(0xffffffffu, w, o);
                if (lane >= o) w += t;
            }
            wsum[lane] = w;
        }
        __syncthreads();
        int base = running + (wid ? wsum[wid - 1] : 0) + ss - s;
        int4 o4; o4.x = base; o4.y = base + v.x; o4.z = o4.y + v.y; o4.w = o4.z + v.z;
        ((int4*)g_off)[c*1024 + tid] = o4;
        ((int4*)g_cur)[c*1024 + tid] = o4;
        running += wsum[31];
        __syncthreads();
    }
    if (tid == 0) g_off[NN] = EE;
}

__global__ void k_fill(const void* __restrict__ ei) {
    int e = blockIdx.x*256 + threadIdx.x;
    int src, dst;
    if (g_is64) {
        const long long* p = (const long long*)ei;
        src = (int)p[e]; dst = (int)p[EE + e];
    } else {
        const int* p = (const int*)ei;
        src = p[e]; dst = p[EE + e];
    }
    int pos = atomicAdd(&g_cur[dst], 1);
    g_srcl[pos] = src;
}

// ---- fused gather + update (f32x2) ----
__global__ void k_gup(const float* __restrict__ hin, float* __restrict__ hout) {
    __shared__ __align__(16) float4 sAB[2048];             // 32KB packed weights
    __shared__ __align__(16) unsigned long long sc[32];    // bias pairs
    __shared__ float2 smh[8][64];                          // per-warp (m,h) broadcast
    int tid = threadIdx.x;
    for (int e = tid; e < 2048; e += 256) sAB[e] = ((const float4*)g_AB)[e];
    if (tid < 32) sc[tid] = ((const unsigned long long*)g_c)[tid];
    __syncthreads();
    int lane = tid & 31, warp = tid >> 5;
    const ulonglong2* wAB = (const ulonglong2*)sAB;
    for (int node = blockIdx.x*8 + warp; node < NN; node += gridDim.x*8) {
        int o0 = g_off[node], o1 = g_off[node + 1];
        float m_lo = 0.f, m_hi = 0.f;
        for (int b = o0; b < o1; b += 32) {
            int n = o1 - b; n = n > 32 ? 32 : n;
            int idx = (lane < n) ? g_srcl[b + lane] : 0;
            for (int j = 0; j < n; ++j) {
                int s = __shfl_sync(0xffffffffu, idx, j);
                m_lo += hin[s*64 + lane];
                m_hi += hin[s*64 + 32 + lane];
            }
        }
        float h_lo = hin[node*64 + lane], h_hi = hin[node*64 + 32 + lane];
        smh[warp][lane]      = make_float2(m_lo, h_lo);
        smh[warp][32 + lane] = make_float2(m_hi, h_hi);
        __syncwarp();
        unsigned long long acc = sc[lane];
        #pragma unroll 16
        for (int k = 0; k < 64; ++k) {
            ulonglong2 wv = wAB[k*32 + lane];
            float2 mh = smh[warp][k];
            acc = ff2(wv.x, pk2(mh.x, mh.x), acc);
            acc = ff2(wv.y, pk2(mh.y, mh.y), acc);
        }
        __syncwarp();
        float2 a = up2(acc);
        float a0 = fmaxf(a.x, 0.f), a1 = fmaxf(a.y, 0.f);
        float s = a0*a0 + a1*a1;
        #pragma unroll
        for (int off = 16; off; off >>= 1) s += __shfl_xor_sync(0xffffffffu, s, off);
        float rn = rsqrtf(s);
        ((float2*)hout)[node*32 + lane] = make_float2(a0*rn, a1*rn);
    }
}

// ---- Ag[g][o][i] = sum_j W5[o][i*64+j] * last[g][j]; block per o ----
__global__ void k_ag(const float* __restrict__ W5, const float* __restrict__ hfin) {
    __shared__ __align__(16) float sWT[64*64];  // [j][i]
    int o = blockIdx.x, tid = threadIdx.x;
    for (int e = tid; e < 4096; e += 256) {
        int j = e >> 6, i = e & 63;
        sWT[j*64 + i] = W5[o*4096 + i*64 + j];   // store conflict-free (i inner)
    }
    __syncthreads();
    int lane = tid & 31, warp = tid >> 5;
    const unsigned long long* wp = (const unsigned long long*)sWT;
    for (int g = warp; g < GG; g += 8) {
        const float* lp = hfin + (g*128 + 127)*64;
        float l_lo = lp[lane], l_hi = lp[32 + lane];
        unsigned long long acc = 0;
        #pragma unroll
        for (int j = 0; j < 32; ++j) {
            float lj = __shfl_sync(0xffffffffu, l_lo, j);
            acc = ff2(wp[j*32 + lane], pk2(lj, lj), acc);
        }
        #pragma unroll
        for (int j = 0; j < 32; ++j) {
            float lj = __shfl_sync(0xffffffffu, l_hi, j);
            acc = ff2(wp[(j + 32)*32 + lane], pk2(lj, lj), acc);
        }
        ((float2*)(g_Ag + g*4096 + o*64))[lane] = up2(acc);   // coalesced pairs
    }
}

// ---- y1 = others @ Ag.T + b5; block per graph (f32x2) ----
__global__ void k_y1(const float* __restrict__ hfin, const float* __restrict__ b5,
                     float* __restrict__ y1) {
    __shared__ __align__(16) float sAgT[64*64];  // [i][o]
    __shared__ unsigned long long sb5[32];
    __shared__ float smx[8][64];
    int g = blockIdx.x, tid = threadIdx.x;
    for (int e = tid; e < 4096; e += 256) {
        int o = e & 63, i = e >> 6;              // o inner: conflict-free SMEM store
        sAgT[i*64 + o] = g_Ag[g*4096 + o*64 + i];
    }
    if (tid < 32) sb5[tid] = ((const unsigned long long*)b5)[tid];
    __syncthreads();
    int lane = tid & 31, warp = tid >> 5;
    const unsigned long long* ap = (const unsigned long long*)sAgT;
    for (int p = warp; p < 127; p += 8) {
        const float* xp = hfin + (g*128 + p)*64;
        smx[warp][lane]      = xp[lane];
        smx[warp][32 + lane] = xp[32 + lane];
        __syncwarp();
        unsigned long long acc = sb5[lane];
        #pragma unroll 16
        for (int i = 0; i < 64; ++i) {
            float xi = smx[warp][i];
            acc = ff2(ap[i*32 + lane], pk2(xi, xi), acc);
        }
        __syncwarp();
        ((float2*)y1)[(g*127 + p)*32 + lane] = up2(acc);
    }
}

// ---- head (f32x2) ----
__global__ void k_head(const float* __restrict__ y1,
                       const float* __restrict__ Wd1, const float* __restrict__ bd1,
                       const float* __restrict__ Wd2, const float* __restrict__ bd2,
                       float* __restrict__ out) {
    __shared__ __align__(16) float sW1T[64*128];  // [k][j]
    __shared__ __align__(16) float sb1[128];
    __shared__ __align__(16) float sW2[128];
    __shared__ float smy[8][64];
    int tid = threadIdx.x;
    for (int e = tid; e < 8192; e += 256) {
        int j = e >> 6, k = e & 63;
        sW1T[k*128 + j] = Wd1[e];
    }
    if (tid < 128) { sb1[tid] = bd1[tid]; sW2[tid] = Wd2[tid]; }
    __syncthreads();
    float bias2 = bd2[0];
    int lane = tid & 31, warp = tid >> 5;
    const ulonglong2* wp = (const ulonglong2*)sW1T;
    for (int row = blockIdx.x*8 + warp; row < ROWS; row += gridDim.x*8) {
        smy[warp][lane]      = y1[row*64 + lane];
        smy[warp][32 + lane] = y1[row*64 + 32 + lane];
        __syncwarp();
        unsigned long long z01 = pk2(sb1[4*lane], sb1[4*lane + 1]);
        unsigned long long z23 = pk2(sb1[4*lane + 2], sb1[4*lane + 3]);
        #pragma unroll 16
        for (int k = 0; k < 64; ++k) {
            float yk = smy[warp][k];
            unsigned long long yy = pk2(yk, yk);
            ulonglong2 wv = wp[k*32 + lane];
            z01 = ff2(wv.x, yy, z01);
            z23 = ff2(wv.y, yy, z23);
        }
        __syncwarp();
        float2 za = up2(z01), zb = up2(z23);
        float4 w2 = *(float4*)&sW2[4*lane];
        float acc = fmaxf(za.x, 0.f)*w2.x + fmaxf(za.y, 0.f)*w2.y +
                    fmaxf(zb.x, 0.f)*w2.z + fmaxf(zb.y, 0.f)*w2.w;
        #pragma unroll
        for (int off = 16; off; off >>= 1) acc += __shfl_xor_sync(0xffffffffu, acc, off);
        if (lane == 0) out[row] = acc + bias2;
    }
}

extern "C" void kernel_launch(void* const* d_in, const int* in_sizes, int n_in,
                              void* d_out, int out_size) {
    const float* x = (const float*)d_in[0];
    const void*  ei = d_in[1];
    int base = (in_sizes[3] == 1) ? 4 : 3;
    const float* W1  = (const float*)d_in[base + 0];
    const float* b1  = (const float*)d_in[base + 1];
    const float* W2  = (const float*)d_in[base + 2];
    const float* b2  = (const float*)d_in[base + 3];
    const float* W3  = (const float*)d_in[base + 4];
    const float* b3  = (const float*)d_in[base + 5];
    const float* W4  = (const float*)d_in[base + 6];
    const float* b4  = (const float*)d_in[base + 7];
    const float* W5  = (const float*)d_in[base + 8];
    const float* b5  = (const float*)d_in[base + 9];
    const float* Wd1 = (const float*)d_in[base + 10];
    const float* bd1 = (const float*)d_in[base + 11];
    const float* Wd2 = (const float*)d_in[base + 12];
    const float* bd2 = (const float*)d_in[base + 13];
    float* out = (float*)d_out;

    float *hA = nullptr, *hB = nullptr;
    void* curp = nullptr;
    cudaGetSymbolAddress((void**)&hA, g_h);
    cudaGetSymbolAddress((void**)&hB, g_m);
    cudaGetSymbolAddress(&curp, g_cur);

    k_detect<<<1, 1024>>>((const int*)ei);
    cudaMemsetAsync(curp, 0, NN*sizeof(int));
    k_pre<<<17, 256>>>(W2, b2, W3, b3, W4, b4);
    k_in<<<512, 256>>>(x, W1, b1);
    k_hist<<<EE/256, 256>>>(ei);
    k_scan<<<1, 1024>>>();
    k_fill<<<EE/256, 256>>>(ei);
    k_gup<<<512, 256>>>(hA, hB);
    k_gup<<<512, 256>>>(hB, hA);
    k_gup<<<512, 256>>>(hA, hB);
    k_ag<<<64, 256>>>(W5, hB);
    k_y1<<<256, 256>>>(hB, b5, hA);
    k_head<<<296, 256>>>(hA, Wd1, bd1, Wd2, bd2, out);
}